// round 3
// baseline (speedup 1.0000x reference)
#include <cuda_runtime.h>
#include <math.h>

#define N_TOTAL 4096
#define T_ 32
#define D_ 158
#define NEWS_ 1024
#define AGGW 1184          // 1024 news + 158 price + 2 pad (74 * 16)
#define NTILES 74

// out layout (float32): pred | rw | hidden | topk | rw
#define OFF_PRED 0
#define OFF_RW1 4096
#define OFF_HID 266240
#define OFF_TOPK 528384
#define OFF_RW2 536576

__device__ float g_agg[N_TOTAL * AGGW];

// ---------------------------------------------------------------------------
// Kernel A (round-1 proven): masked news mean + price mean -> g_agg
// ---------------------------------------------------------------------------
__global__ void kernelA(const float* __restrict__ price,
                        const float* __restrict__ news,
                        const float* __restrict__ mask) {
    int n = blockIdx.x;
    int tid = threadIdx.x;
    __shared__ float sm[T_];
    __shared__ float sinv;
    if (tid < T_) sm[tid] = mask[n * T_ + tid];
    __syncthreads();
    if (tid == 0) {
        float s = 0.f;
        #pragma unroll
        for (int t = 0; t < T_; t++) s += sm[t];
        sinv = 1.0f / fmaxf(s, 1e-6f);
    }
    __syncthreads();

    const float4* news4 = (const float4*)(news + (size_t)n * T_ * NEWS_);
    float4 acc = make_float4(0.f, 0.f, 0.f, 0.f);
    #pragma unroll 4
    for (int t = 0; t < T_; t++) {
        float mt = sm[t];
        float4 v = news4[t * 256 + tid];
        acc.x += mt * v.x; acc.y += mt * v.y;
        acc.z += mt * v.z; acc.w += mt * v.w;
    }
    float inv = sinv;
    acc.x *= inv; acc.y *= inv; acc.z *= inv; acc.w *= inv;
    ((float4*)(g_agg + (size_t)n * AGGW))[tid] = acc;

    if (tid < D_) {
        const float* p = price + (size_t)n * T_ * D_ + tid;
        float a = 0.f;
        #pragma unroll 4
        for (int t = 0; t < T_; t++) a += p[t * D_];
        g_agg[(size_t)n * AGGW + NEWS_ + tid] = a * (1.0f / 32.0f);
    } else if (tid < 160) {
        g_agg[(size_t)n * AGGW + NEWS_ + tid] = 0.0f;
    }
}

// ---------------------------------------------------------------------------
// Kernel B: router GEMM (32x1184x128, double-buffered) + tanh + gate GEMM
//           + topk/softmax/experts/attention/output. 128 blocks x 256 thr.
// ---------------------------------------------------------------------------
struct SmemB {
    union {
        struct {
            float A[2][32][16];     // 4 KB
            float B[2][16][128];    // 16 KB
        } db;
        float h[32][128];           // 16 KB
    } u;
    float gate[128][64];            // 32 KB
    float wexp[64][64];             // 16 KB  [h][g*8+e]
    float wq[8][64], wk[8][64], wv[8][64], wo[8][64];  // 8 KB [e][g*8+f]
    float eb[64], qb[64], kb[64], vb[64], ob[64], gb[64];
    float rb[128];
    float h32[32][64];              // 8 KB
    float eo[4][64], q[4][64], kk_[4][64], v[4][64], att[4][64], wbuf[4][64];
    int   i1[4], i2[4];
    float v1[4], den[4];
};

extern __shared__ unsigned char smem_raw[];

__global__ void __launch_bounds__(256, 1)
kernelB(const float* __restrict__ router_W,
        const float* __restrict__ router_b,
        const float* __restrict__ gate_W,
        const float* __restrict__ gate_b,
        const float* __restrict__ expert_W,
        const float* __restrict__ expert_b,
        const float* __restrict__ wq, const float* __restrict__ wq_b,
        const float* __restrict__ wk, const float* __restrict__ wk_b,
        const float* __restrict__ wv, const float* __restrict__ wv_b,
        const float* __restrict__ wo, const float* __restrict__ wo_b,
        float* __restrict__ out) {
    SmemB& s = *reinterpret_cast<SmemB*>(smem_raw);
    const int tid = threadIdx.x;
    const int n0 = blockIdx.x * 32;

    // ---- stage small weights ----
    for (int idx = tid; idx < 128 * 64; idx += 256)
        s.gate[idx >> 6][idx & 63] = gate_W[idx];
    for (int idx = tid; idx < 4096; idx += 256) {
        int ge = idx >> 6, h = idx & 63;
        s.wexp[h][ge] = expert_W[idx];
    }
    for (int idx = tid; idx < 512; idx += 256) {
        int g = idx >> 6, f = (idx >> 3) & 7, e = idx & 7;
        int dst = e * 64 + g * 8 + f;
        ((float*)s.wq)[dst] = wq[idx];
        ((float*)s.wk)[dst] = wk[idx];
        ((float*)s.wv)[dst] = wv[idx];
        ((float*)s.wo)[dst] = wo[idx];
    }
    if (tid < 64) {
        s.eb[tid] = expert_b[tid];
        s.qb[tid] = wq_b[tid]; s.kb[tid] = wk_b[tid];
        s.vb[tid] = wv_b[tid]; s.ob[tid] = wo_b[tid];
        s.gb[tid] = gate_b[tid];
    }
    if (tid < 128) s.rb[tid] = router_b[tid];

    // ---- router GEMM with double buffer + register staging ----
    const int tr = tid >> 5;   // 0..7 -> rows tr*4..tr*4+3
    const int tc = tid & 31;   // cols tc*4..
    float acc[4][4] = {};
    float ra[2], rbw[8];

    // precompute A-load coords for this thread
    const int ar0 = tid >> 4, ac0 = tid & 15;          // elem tid
    const int ar1 = (tid + 256) >> 4, ac1 = ac0;       // elem tid+256

    // prologue: tile 0
    ra[0] = g_agg[(size_t)(n0 + ar0) * AGGW + ac0];
    ra[1] = g_agg[(size_t)(n0 + ar1) * AGGW + ac1];
    #pragma unroll
    for (int i = 0; i < 8; i++) {
        int idx = tid + i * 256;
        int kk = idx >> 7, j = idx & 127;
        rbw[i] = router_W[(158 + kk) * 128 + j];   // k0=0: news region
    }
    s.u.db.A[0][ar0][ac0] = ra[0];
    s.u.db.A[0][ar1][ac1] = ra[1];
    #pragma unroll
    for (int i = 0; i < 8; i++) {
        int idx = tid + i * 256;
        s.u.db.B[0][idx >> 7][idx & 127] = rbw[i];
    }
    __syncthreads();

    for (int t = 0; t < NTILES; t++) {
        const int cur = t & 1;
        if (t < NTILES - 1) {
            int k0 = (t + 1) * 16;
            ra[0] = g_agg[(size_t)(n0 + ar0) * AGGW + k0 + ac0];
            ra[1] = g_agg[(size_t)(n0 + ar1) * AGGW + k0 + ac1];
            #pragma unroll
            for (int i = 0; i < 8; i++) {
                int idx = tid + i * 256;
                int kk = idx >> 7, j = idx & 127;
                int krow = k0 + kk;
                int wrow = (krow < 1024) ? (158 + krow) : min(krow - 1024, 157);
                rbw[i] = router_W[wrow * 128 + j];
            }
        }
        #pragma unroll
        for (int k = 0; k < 16; k++) {
            float a0 = s.u.db.A[cur][tr * 4 + 0][k];
            float a1 = s.u.db.A[cur][tr * 4 + 1][k];
            float a2 = s.u.db.A[cur][tr * 4 + 2][k];
            float a3 = s.u.db.A[cur][tr * 4 + 3][k];
            float4 b = *(const float4*)&s.u.db.B[cur][k][tc * 4];
            acc[0][0] += a0 * b.x; acc[0][1] += a0 * b.y; acc[0][2] += a0 * b.z; acc[0][3] += a0 * b.w;
            acc[1][0] += a1 * b.x; acc[1][1] += a1 * b.y; acc[1][2] += a1 * b.z; acc[1][3] += a1 * b.w;
            acc[2][0] += a2 * b.x; acc[2][1] += a2 * b.y; acc[2][2] += a2 * b.z; acc[2][3] += a2 * b.w;
            acc[3][0] += a3 * b.x; acc[3][1] += a3 * b.y; acc[3][2] += a3 * b.z; acc[3][3] += a3 * b.w;
        }
        if (t < NTILES - 1) {
            const int nxt = cur ^ 1;
            s.u.db.A[nxt][ar0][ac0] = ra[0];
            s.u.db.A[nxt][ar1][ac1] = ra[1];
            #pragma unroll
            for (int i = 0; i < 8; i++) {
                int idx = tid + i * 256;
                s.u.db.B[nxt][idx >> 7][idx & 127] = rbw[i];
            }
        }
        __syncthreads();
    }

    // ---- tanh, stash h into union (GEMM buffers dead) ----
    #pragma unroll
    for (int i = 0; i < 4; i++) {
        #pragma unroll
        for (int jj = 0; jj < 4; jj++) {
            int j = tc * 4 + jj;
            s.u.h[tr * 4 + i][j] = tanhf(acc[i][jj] + s.rb[j]);
        }
    }
    __syncthreads();

    // ---- gate GEMM: hidden[32][64] = h @ gate_W + gate_b ----
    {
        int r = tid >> 3;
        int c0 = (tid & 7) * 8;
        float hacc[8] = {};
        #pragma unroll 4
        for (int kk = 0; kk < 128; kk++) {
            float hv = s.u.h[r][kk];
            float4 g0 = *(const float4*)&s.gate[kk][c0];
            float4 g1 = *(const float4*)&s.gate[kk][c0 + 4];
            hacc[0] += hv * g0.x; hacc[1] += hv * g0.y;
            hacc[2] += hv * g0.z; hacc[3] += hv * g0.w;
            hacc[4] += hv * g1.x; hacc[5] += hv * g1.y;
            hacc[6] += hv * g1.z; hacc[7] += hv * g1.w;
        }
        float* out_hid = out + OFF_HID;
        #pragma unroll
        for (int c = 0; c < 8; c++) {
            float val = hacc[c] + s.gb[c0 + c];
            out_hid[(size_t)(n0 + r) * 64 + c0 + c] = val;
            s.h32[r][c0 + c] = val;
        }
    }
    __syncthreads();

    // ---- phase 3: topk / softmax / experts / attention / output ----
    {
        const int grp = tid >> 6;
        const int j = tid & 63;
        const int g = j >> 3;
        const int base = g * 8;
        const int hh = (j & 7) >> 1, d = j & 1;

        float* out_pred = out + OFF_PRED;
        float* out_rw1 = out + OFF_RW1;
        float* out_topk = out + OFF_TOPK;
        float* out_rw2 = out + OFF_RW2;

        for (int it = 0; it < 8; it++) {
            int rl = it * 4 + grp;
            int n = n0 + rl;
            float hj = s.h32[rl][j];

            if (j == 0) {
                float v1 = -1e38f; int i1 = 0;
                #pragma unroll 8
                for (int a = 0; a < 64; a++) {
                    float v = s.h32[rl][a];
                    if (v > v1) { v1 = v; i1 = a; }
                }
                float v2 = -1e38f; int i2 = 0;
                #pragma unroll 8
                for (int a = 0; a < 64; a++) {
                    if (a == i1) continue;
                    float v = s.h32[rl][a];
                    if (v > v2) { v2 = v; i2 = a; }
                }
                s.i1[grp] = i1; s.i2[grp] = i2; s.v1[grp] = v1;
                s.den[grp] = 1.0f + expf(v2 - v1);
            }
            __syncthreads();
            int i1 = s.i1[grp], i2 = s.i2[grp];
            float rw = 0.0f;
            if (j == i1) rw = 1.0f / s.den[grp];
            else if (j == i2) rw = expf(hj - s.v1[grp]) / s.den[grp];

            float eo = s.eb[j];
            #pragma unroll 8
            for (int h = 0; h < 64; h++) eo += s.h32[rl][h] * s.wexp[h][j];
            s.eo[grp][j] = eo;
            __syncthreads();

            float qv = s.qb[j], kv = s.kb[j], vv = s.vb[j];
            #pragma unroll
            for (int e = 0; e < 8; e++) {
                float x = s.eo[grp][base + e];
                qv += x * s.wq[e][j];
                kv += x * s.wk[e][j];
                vv += x * s.wv[e][j];
            }
            s.q[grp][j] = qv; s.kk_[grp][j] = kv; s.v[grp][j] = vv;
            __syncthreads();

            float s0 = 0.f, s1 = 0.f;
            #pragma unroll
            for (int a = 0; a < 4; a++) {
                float qa = s.q[grp][base + 2 * a + d];
                s0 += qa * s.kk_[grp][base + 2 * a];
                s1 += qa * s.kk_[grp][base + 2 * a + 1];
            }
            const float sc = 0.70710678118654752440f;
            s0 *= sc; s1 *= sc;
            float mx = fmaxf(s0, s1);
            float e0 = expf(s0 - mx), e1 = expf(s1 - mx);
            float rs = 1.0f / (e0 + e1);
            float att = (e0 * rs) * s.v[grp][base + 2 * hh]
                      + (e1 * rs) * s.v[grp][base + 2 * hh + 1];
            s.att[grp][j] = att;
            __syncthreads();

            float ag = s.ob[j];
            #pragma unroll
            for (int e = 0; e < 8; e++) ag += s.att[grp][base + e] * s.wo[e][j];

            out_rw1[(size_t)n * 64 + j] = rw;
            out_rw2[(size_t)n * 64 + j] = rw;
            s.wbuf[grp][j] = ag * rw;
            __syncthreads();
            if (j == 0) {
                out_pred[n] = s.wbuf[grp][i1] + s.wbuf[grp][i2];
                out_topk[n * 2 + 0] = (float)i1;
                out_topk[n * 2 + 1] = (float)i2;
            }
            __syncthreads();
        }
    }
}

// ---------------------------------------------------------------------------
extern "C" void kernel_launch(void* const* d_in, const int* in_sizes, int n_in,
                              void* d_out, int out_size) {
    const float* price    = (const float*)d_in[0];
    const float* news     = (const float*)d_in[1];
    const float* mask     = (const float*)d_in[2];
    const float* router_W = (const float*)d_in[3];
    const float* router_b = (const float*)d_in[4];
    const float* gate_W   = (const float*)d_in[5];
    const float* gate_b   = (const float*)d_in[6];
    const float* expert_W = (const float*)d_in[7];
    const float* expert_b = (const float*)d_in[8];
    const float* wq   = (const float*)d_in[9];
    const float* wq_b = (const float*)d_in[10];
    const float* wk   = (const float*)d_in[11];
    const float* wk_b = (const float*)d_in[12];
    const float* wv   = (const float*)d_in[13];
    const float* wv_b = (const float*)d_in[14];
    const float* wo   = (const float*)d_in[15];
    const float* wo_b = (const float*)d_in[16];
    float* out = (float*)d_out;

    kernelA<<<N_TOTAL, 256>>>(price, news, mask);

    cudaFuncSetAttribute(kernelB,
                         cudaFuncAttributeMaxDynamicSharedMemorySize,
                         (int)sizeof(SmemB));
    kernelB<<<128, 256, sizeof(SmemB)>>>(
        router_W, router_b, gate_W, gate_b, expert_W, expert_b,
        wq, wq_b, wk, wk_b, wv, wv_b, wo, wo_b, out);
}